// round 13
// baseline (speedup 1.0000x reference)
#include <cuda_runtime.h>
#include <cuda_bf16.h>
#include <cstdint>

// ----------------------------------------------------------------------------
// SoftAttentionDrop — fused, 512-thread CTA (sm_100 plain target)
//   convW: W -> bf16 hi/lo globals (once)
//   fused: mask = feat @ W.T + b (split-bf16 mma.sync, 3 passes, 16 warps,
//          each warp owns a 16-col N-strip -> acc 32 regs)
//          t = exp(mask); 26x: n=t^5, S=rowsum(n), t*=(1-n/S)
//          w = t*exp(-mask); out = feat*w/0.9
//   iteration: 1 row per 16-lane group, 2 rows sequentially; 8 warps/SMSP
// ----------------------------------------------------------------------------

#define N_DIM   256
#define MTILE   64
#define KC      64
#define NCHUNKS 4
#define KITER   26
#define THREADS 512

#define SM_AHI  0
#define SM_ALO  (MTILE * 128)            // 8192
#define SM_BHI  (2 * MTILE * 128)        // 16384
#define SM_BLO  (SM_BHI + 256 * 128)     // 49152
#define SMEM_TOTAL 81920                 // staging 80KB; mask (64*258*4=66048) overlaps
#define MASK_PITCH 258

typedef unsigned long long u64;

__device__ __align__(16) __nv_bfloat16 g_Whi[N_DIM * N_DIM];
__device__ __align__(16) __nv_bfloat16 g_Wlo[N_DIM * N_DIM];

// ---- helpers ----------------------------------------------------------------

__device__ __forceinline__ uint32_t smem_u32(const void* p) {
    uint32_t a;
    asm("{ .reg .u64 t; cvta.to.shared.u64 t, %1; cvt.u32.u64 %0, t; }"
        : "=r"(a) : "l"(p));
    return a;
}

__device__ __forceinline__ void ldsm_x4(uint32_t* r, uint32_t addr) {
    asm volatile("ldmatrix.sync.aligned.m8n8.x4.shared.b16 {%0,%1,%2,%3}, [%4];"
                 : "=r"(r[0]), "=r"(r[1]), "=r"(r[2]), "=r"(r[3]) : "r"(addr));
}

__device__ __forceinline__ void mma16816(float* d, const uint32_t* a,
                                         uint32_t b0, uint32_t b1) {
    asm volatile(
        "mma.sync.aligned.m16n8k16.row.col.f32.bf16.bf16.f32 "
        "{%0,%1,%2,%3}, {%4,%5,%6,%7}, {%8,%9}, {%0,%1,%2,%3};"
        : "+f"(d[0]), "+f"(d[1]), "+f"(d[2]), "+f"(d[3])
        : "r"(a[0]), "r"(a[1]), "r"(a[2]), "r"(a[3]), "r"(b0), "r"(b1));
}

// packed f32x2
__device__ __forceinline__ u64 pk(float lo, float hi) {
    u64 r; asm("mov.b64 %0, {%1, %2};" : "=l"(r) : "f"(lo), "f"(hi)); return r;
}
__device__ __forceinline__ void upk(float& lo, float& hi, u64 v) {
    asm("mov.b64 {%0, %1}, %2;" : "=f"(lo), "=f"(hi) : "l"(v));
}
__device__ __forceinline__ u64 addx2(u64 a, u64 b) {
    u64 d; asm("add.rn.f32x2 %0, %1, %2;" : "=l"(d) : "l"(a), "l"(b)); return d;
}
__device__ __forceinline__ u64 mulx2(u64 a, u64 b) {
    u64 d; asm("mul.rn.f32x2 %0, %1, %2;" : "=l"(d) : "l"(a), "l"(b)); return d;
}
__device__ __forceinline__ u64 fmax2(u64 a, u64 b, u64 c) {
    u64 d; asm("fma.rn.f32x2 %0, %1, %2, %3;" : "=l"(d) : "l"(a), "l"(b), "l"(c)); return d;
}

// ---- prelude: convert W to bf16 hi/lo --------------------------------------

__global__ void convW_kernel(const float* __restrict__ W) {
    int i = blockIdx.x * 256 + threadIdx.x;
    float v = W[i];
    __nv_bfloat16 h = __float2bfloat16(v);
    g_Whi[i] = h;
    g_Wlo[i] = __float2bfloat16(v - __bfloat162float(h));
}

// ---- fused kernel -------------------------------------------------------------

__global__ void __launch_bounds__(THREADS, 2)
sad_kernel(const float* __restrict__ feat,
           const float* __restrict__ bias,
           float* __restrict__ out,
           int nrows)
{
    extern __shared__ char smem[];
    const uint32_t sbase = smem_u32(smem);
    const int tid = threadIdx.x;
    const int wid = tid >> 5;           // 0..15
    const int lane = tid & 31;
    const int m0 = blockIdx.x * MTILE;
    const int mrows = min(MTILE, nrows - m0);

    float acc[4][2][4];                  // [m-tile][n-subtile(8)][frag]
    #pragma unroll
    for (int a = 0; a < 4; a++)
        #pragma unroll
        for (int b = 0; b < 2; b++)
            #pragma unroll
            for (int c = 0; c < 4; c++) acc[a][b][c] = 0.0f;

    // -------- GEMM over 4 K-chunks of 64 --------
    for (int chunk = 0; chunk < NCHUNKS; chunk++) {
        const int k0 = chunk * KC;

        // stage A: 64 rows x 64 k -> bf16 hi/lo swizzled. 1 thread = one 16B unit.
        {
            int row = tid >> 3;          // 0..63
            int seg = tid & 7;           // 16B unit within 128B row
            float x[8];
            if (row < mrows) {
                const float4* src = (const float4*)(feat + (size_t)(m0 + row) * N_DIM + k0 + seg * 8);
                float4 v0 = __ldg(&src[0]);
                float4 v1 = __ldg(&src[1]);
                x[0] = v0.x; x[1] = v0.y; x[2] = v0.z; x[3] = v0.w;
                x[4] = v1.x; x[5] = v1.y; x[6] = v1.z; x[7] = v1.w;
            } else {
                #pragma unroll
                for (int q = 0; q < 8; q++) x[q] = 0.0f;
            }
            uint32_t hw[4], lw[4];
            #pragma unroll
            for (int j = 0; j < 4; j++) {
                __nv_bfloat162 hh = __floats2bfloat162_rn(x[2 * j], x[2 * j + 1]);
                float r0 = x[2 * j]     - __bfloat162float(hh.x);
                float r1 = x[2 * j + 1] - __bfloat162float(hh.y);
                __nv_bfloat162 ll = __floats2bfloat162_rn(r0, r1);
                hw[j] = *(uint32_t*)&hh;
                lw[j] = *(uint32_t*)&ll;
            }
            int phys = row * 128 + ((seg ^ (row & 7)) << 4);
            *(uint4*)(smem + SM_AHI + phys) = make_uint4(hw[0], hw[1], hw[2], hw[3]);
            *(uint4*)(smem + SM_ALO + phys) = make_uint4(lw[0], lw[1], lw[2], lw[3]);
        }
        // stage B: Whi/Wlo chunk [256 x 64] as 16B units, swizzled
        {
            const uint4* ghi = (const uint4*)g_Whi;
            const uint4* glo = (const uint4*)g_Wlo;
            #pragma unroll
            for (int i = 0; i < 4; i++) {
                int gidx = tid + THREADS * i;   // 0..2047
                int row = gidx >> 3;
                int u = gidx & 7;
                int gword = row * 32 + (k0 >> 3) + u;
                int phys = row * 128 + ((u ^ (row & 7)) << 4);
                *(uint4*)(smem + SM_BHI + phys) = __ldg(&ghi[gword]);
                *(uint4*)(smem + SM_BLO + phys) = __ldg(&glo[gword]);
            }
        }
        __syncthreads();

        #pragma unroll
        for (int ks = 0; ks < 4; ks++) {
            uint32_t BH[4], BL[4];
            {
                int n = wid * 16 + (lane & 15);
                int u = ks * 2 + (lane >> 4);
                uint32_t ph = (uint32_t)(n * 128 + ((u ^ (n & 7)) << 4));
                ldsm_x4(BH, sbase + SM_BHI + ph);
                ldsm_x4(BL, sbase + SM_BLO + ph);
            }
            #pragma unroll
            for (int mt = 0; mt < 4; mt++) {
                int r = mt * 16 + (lane & 15);
                int u = ks * 2 + (lane >> 4);
                uint32_t ph = (uint32_t)(r * 128 + ((u ^ (r & 7)) << 4));
                uint32_t AF[4];
                ldsm_x4(AF, sbase + SM_AHI + ph);
                mma16816(acc[mt][0], AF, BH[0], BH[2]);   // hi*Bhi
                mma16816(acc[mt][1], AF, BH[1], BH[3]);
                mma16816(acc[mt][0], AF, BL[0], BL[2]);   // hi*Blo
                mma16816(acc[mt][1], AF, BL[1], BL[3]);
                ldsm_x4(AF, sbase + SM_ALO + ph);
                mma16816(acc[mt][0], AF, BH[0], BH[2]);   // lo*Bhi
                mma16816(acc[mt][1], AF, BH[1], BH[3]);
            }
        }
        __syncthreads();   // staging buffers reused next chunk
    }

    // -------- epilogue: acc + bias -> mask smem (pitch 258) --------
    {
        float* mptr = (float*)smem;
        #pragma unroll
        for (int nt = 0; nt < 2; nt++) {
            int c = wid * 16 + nt * 8 + 2 * (lane & 3);
            float b0 = __ldg(&bias[c]);
            float b1 = __ldg(&bias[c + 1]);
            #pragma unroll
            for (int mt = 0; mt < 4; mt++) {
                int r0 = mt * 16 + (lane >> 2);
                int r1 = r0 + 8;
                mptr[r0 * MASK_PITCH + c]     = acc[mt][nt][0] + b0;
                mptr[r0 * MASK_PITCH + c + 1] = acc[mt][nt][1] + b1;
                mptr[r1 * MASK_PITCH + c]     = acc[mt][nt][2] + b0;
                mptr[r1 * MASK_PITCH + c + 1] = acc[mt][nt][3] + b1;
            }
        }
    }
    __syncthreads();

    // -------- iterations: 1 row per 16-lane group, 2 rows sequentially -----
    // state: t = exp(mask)*w ; num = t^5 ; t *= (1 - num/S) ; w = t*exp(-mask)
    {
        const float* mptr = (const float*)smem;
        const float inv09 = 1.0f / 0.9f;
        const int g = lane & 15;
        const int grp = lane >> 4;

        for (int rr = 0; rr < 2; rr++) {
            const int r = wid * 4 + grp * 2 + rr;   // 0..63 across CTA
            const float* mrow = mptr + r * MASK_PITCH + g * 2;

            u64 T[8];
            #pragma unroll
            for (int p = 0; p < 8; p++) {
                float2 a = *(const float2*)(mrow + 32 * p);
                T[p] = pk(__expf(a.x), __expf(a.y));    // t = e^mask (w=1)
            }

            for (int it = 0; it < KITER; it++) {
                u64 n[8];
                #pragma unroll
                for (int p = 0; p < 8; p++) {
                    u64 x2 = mulx2(T[p], T[p]);
                    u64 x4 = mulx2(x2, x2);
                    n[p] = mulx2(x4, T[p]);             // t^5
                }
                u64 s = addx2(addx2(addx2(n[0], n[1]), addx2(n[2], n[3])),
                              addx2(addx2(n[4], n[5]), addx2(n[6], n[7])));
                float slo, shi;
                upk(slo, shi, s);
                float S = slo + shi;
                #pragma unroll
                for (int o = 8; o > 0; o >>= 1)         // within 16-lane halves
                    S += __shfl_xor_sync(0xffffffffu, S, o);
                float q = -__fdividef(1.0f, S);
                u64 R = pk(q, q);
                #pragma unroll
                for (int p = 0; p < 8; p++)
                    T[p] = fmax2(mulx2(n[p], R), T[p], T[p]);   // t *= (1 - n/S)
            }

            const int gr = m0 + r;
            if (gr < nrows) {
                const float* fr = feat + (size_t)gr * N_DIM + g * 2;
                float* orow = out + (size_t)gr * N_DIM + g * 2;
                #pragma unroll
                for (int p = 0; p < 8; p++) {
                    float2 a = *(const float2*)(mrow + 32 * p);
                    u64 wv = mulx2(T[p], pk(__expf(-a.x), __expf(-a.y)));
                    float2 f = __ldg((const float2*)(fr + 32 * p));
                    float wlo, whi;
                    upk(wlo, whi, wv);
                    float2 o2;
                    o2.x = f.x * wlo * inv09;
                    o2.y = f.y * whi * inv09;
                    *(float2*)(orow + 32 * p) = o2;
                }
            }
        }
    }
}

// ---- launcher ---------------------------------------------------------------

extern "C" void kernel_launch(void* const* d_in, const int* in_sizes, int n_in,
                              void* d_out, int out_size) {
    const float* feat = (const float*)d_in[0];
    const float* W    = (const float*)d_in[1];
    const float* b    = (const float*)d_in[2];
    float* out        = (float*)d_out;
    const int nrows = in_sizes[0] / N_DIM;
    const int grid = (nrows + MTILE - 1) / MTILE;

    convW_kernel<<<N_DIM, 256>>>(W);

    cudaFuncSetAttribute(sad_kernel,
                         cudaFuncAttributeMaxDynamicSharedMemorySize, SMEM_TOTAL);
    sad_kernel<<<grid, THREADS, SMEM_TOTAL>>>(feat, b, out, nrows);
}

// round 14
// speedup vs baseline: 1.0459x; 1.0459x over previous
#include <cuda_runtime.h>
#include <cuda_bf16.h>
#include <cstdint>

// ----------------------------------------------------------------------------
// SoftAttentionDrop (sm_100 plain target -> mma.sync bf16 split GEMM)
//   prelude: W -> bf16 hi/lo in __device__ globals (once)
//   main:    mask = feat @ W.T + b (split-bf16 mma.sync, 3 passes)
//            GEMM staging PIPELINED: 8 K-chunks of 32, k-interleaved double
//            buffers; A(c+1) prefetched to regs, B(c+1) via cp.async, both
//            issued before mma(c) so LDG latency hides under tensor work.
//            t = exp(mask); 26x: n=t^5, S=rowsum(n), t*=(1-n/S)
//            w = t*exp(-mask); out = feat*w/0.9
//   iteration layout: 1 row per 16-lane group, 2 sets in flight per warp
// ----------------------------------------------------------------------------

#define N_DIM   256
#define MTILE   64
#define KC      32
#define NCHUNKS 8
#define KITER   26

#define SM_AHI  0
#define SM_ALO  (MTILE * 128)            // 8192   (64 rows x 128B, 2 k-halves)
#define SM_BHI  (2 * MTILE * 128)        // 16384
#define SM_BLO  (SM_BHI + 256 * 128)     // 49152  (256 rows x 128B, 2 k-halves)
#define SMEM_TOTAL 81920                 // staging 80KB; mask (64*258*4) overlaps
#define MASK_PITCH 258

typedef unsigned long long u64;

__device__ __align__(16) __nv_bfloat16 g_Whi[N_DIM * N_DIM];
__device__ __align__(16) __nv_bfloat16 g_Wlo[N_DIM * N_DIM];

// ---- helpers ----------------------------------------------------------------

__device__ __forceinline__ uint32_t smem_u32(const void* p) {
    uint32_t a;
    asm("{ .reg .u64 t; cvta.to.shared.u64 t, %1; cvt.u32.u64 %0, t; }"
        : "=r"(a) : "l"(p));
    return a;
}

__device__ __forceinline__ void ldsm_x4(uint32_t* r, uint32_t addr) {
    asm volatile("ldmatrix.sync.aligned.m8n8.x4.shared.b16 {%0,%1,%2,%3}, [%4];"
                 : "=r"(r[0]), "=r"(r[1]), "=r"(r[2]), "=r"(r[3]) : "r"(addr));
}

__device__ __forceinline__ void mma16816(float* d, const uint32_t* a,
                                         uint32_t b0, uint32_t b1) {
    asm volatile(
        "mma.sync.aligned.m16n8k16.row.col.f32.bf16.bf16.f32 "
        "{%0,%1,%2,%3}, {%4,%5,%6,%7}, {%8,%9}, {%0,%1,%2,%3};"
        : "+f"(d[0]), "+f"(d[1]), "+f"(d[2]), "+f"(d[3])
        : "r"(a[0]), "r"(a[1]), "r"(a[2]), "r"(a[3]), "r"(b0), "r"(b1));
}

#define CP_ASYNC16(dst, src) \
    asm volatile("cp.async.cg.shared.global [%0], [%1], 16;" \
                 :: "r"(dst), "l"(src))
#define CP_COMMIT() asm volatile("cp.async.commit_group;")
#define CP_WAIT(N)  asm volatile("cp.async.wait_group %0;" :: "n"(N))

// packed f32x2
__device__ __forceinline__ u64 pk(float lo, float hi) {
    u64 r; asm("mov.b64 %0, {%1, %2};" : "=l"(r) : "f"(lo), "f"(hi)); return r;
}
__device__ __forceinline__ void upk(float& lo, float& hi, u64 v) {
    asm("mov.b64 {%0, %1}, %2;" : "=f"(lo), "=f"(hi) : "l"(v));
}
__device__ __forceinline__ u64 addx2(u64 a, u64 b) {
    u64 d; asm("add.rn.f32x2 %0, %1, %2;" : "=l"(d) : "l"(a), "l"(b)); return d;
}
__device__ __forceinline__ u64 mulx2(u64 a, u64 b) {
    u64 d; asm("mul.rn.f32x2 %0, %1, %2;" : "=l"(d) : "l"(a), "l"(b)); return d;
}
__device__ __forceinline__ u64 fmax2(u64 a, u64 b, u64 c) {
    u64 d; asm("fma.rn.f32x2 %0, %1, %2, %3;" : "=l"(d) : "l"(a), "l"(b), "l"(c)); return d;
}

// ---- prelude: convert W to bf16 hi/lo --------------------------------------

__global__ void convW_kernel(const float* __restrict__ W) {
    int i = blockIdx.x * 256 + threadIdx.x;
    float v = W[i];
    __nv_bfloat16 h = __float2bfloat16(v);
    g_Whi[i] = h;
    g_Wlo[i] = __float2bfloat16(v - __bfloat162float(h));
}

// ---- main kernel ------------------------------------------------------------

__global__ void __launch_bounds__(256, 2)
sad_kernel(const float* __restrict__ feat,
           const float* __restrict__ bias,
           float* __restrict__ out,
           int nrows)
{
    extern __shared__ char smem[];
    const uint32_t sbase = smem_u32(smem);
    const int tid = threadIdx.x;
    const int wid = tid >> 5;
    const int lane = tid & 31;
    const int m0 = blockIdx.x * MTILE;
    const int mrows = min(MTILE, nrows - m0);

    float acc[4][4][4];
    #pragma unroll
    for (int a = 0; a < 4; a++)
        #pragma unroll
        for (int b = 0; b < 4; b++)
            #pragma unroll
            for (int c = 0; c < 4; c++) acc[a][b][c] = 0.0f;

    // -------- GEMM over 8 K-chunks of 32, pipelined staging ----------------
    const int arow = tid >> 2;        // 0..63 (A staging row)
    const int au   = tid & 3;         // 16B unit within 64B half-row
    const uint4* ghi = (const uint4*)g_Whi;
    const uint4* glo = (const uint4*)g_Wlo;

    float xc[8], xn[8];

    // prologue: A(0) -> regs, B(0) -> cp.async group
    {
        if (arow < mrows) {
            const float4* src = (const float4*)(feat + (size_t)(m0 + arow) * N_DIM + au * 8);
            float4 v0 = __ldg(&src[0]);
            float4 v1 = __ldg(&src[1]);
            xc[0] = v0.x; xc[1] = v0.y; xc[2] = v0.z; xc[3] = v0.w;
            xc[4] = v1.x; xc[5] = v1.y; xc[6] = v1.z; xc[7] = v1.w;
        } else {
            #pragma unroll
            for (int q = 0; q < 8; q++) xc[q] = 0.0f;
        }
        #pragma unroll
        for (int i = 0; i < 4; i++) {
            int idx = tid + 256 * i;          // 0..1023
            int row = idx >> 2;
            int u = idx & 3;                  // u_global = u (chunk 0)
            uint32_t phys = (uint32_t)(row * 128 + ((u ^ (row & 7)) << 4));
            CP_ASYNC16(sbase + SM_BHI + phys, &ghi[row * 32 + u]);
            CP_ASYNC16(sbase + SM_BLO + phys, &glo[row * 32 + u]);
        }
        CP_COMMIT();
    }

    for (int c = 0; c < NCHUNKS; c++) {
        const int half = c & 1;

        // prefetch chunk c+1: A -> regs, B -> cp.async (other half)
        if (c + 1 < NCHUNKS) {
            if (arow < mrows) {
                const float4* src = (const float4*)(feat + (size_t)(m0 + arow) * N_DIM
                                                    + (c + 1) * KC + au * 8);
                float4 v0 = __ldg(&src[0]);
                float4 v1 = __ldg(&src[1]);
                xn[0] = v0.x; xn[1] = v0.y; xn[2] = v0.z; xn[3] = v0.w;
                xn[4] = v1.x; xn[5] = v1.y; xn[6] = v1.z; xn[7] = v1.w;
            } else {
                #pragma unroll
                for (int q = 0; q < 8; q++) xn[q] = 0.0f;
            }
            const int nhalf = (c + 1) & 1;
            #pragma unroll
            for (int i = 0; i < 4; i++) {
                int idx = tid + 256 * i;
                int row = idx >> 2;
                int u = idx & 3;
                int ug = nhalf * 4 + u;
                uint32_t phys = (uint32_t)(row * 128 + ((ug ^ (row & 7)) << 4));
                CP_ASYNC16(sbase + SM_BHI + phys, &ghi[row * 32 + (c + 1) * 4 + u]);
                CP_ASYNC16(sbase + SM_BLO + phys, &glo[row * 32 + (c + 1) * 4 + u]);
            }
            CP_COMMIT();
        }

        // convert + store A(c) (regs -> smem, one uint4 per buffer)
        {
            uint32_t hw[4], lw[4];
            #pragma unroll
            for (int j = 0; j < 4; j++) {
                __nv_bfloat162 hh = __floats2bfloat162_rn(xc[2 * j], xc[2 * j + 1]);
                float r0 = xc[2 * j]     - __bfloat162float(hh.x);
                float r1 = xc[2 * j + 1] - __bfloat162float(hh.y);
                __nv_bfloat162 ll = __floats2bfloat162_rn(r0, r1);
                hw[j] = *(uint32_t*)&hh;
                lw[j] = *(uint32_t*)&ll;
            }
            int ug = half * 4 + au;
            uint32_t phys = (uint32_t)(arow * 128 + ((ug ^ (arow & 7)) << 4));
            *(uint4*)(smem + SM_AHI + phys) = make_uint4(hw[0], hw[1], hw[2], hw[3]);
            *(uint4*)(smem + SM_ALO + phys) = make_uint4(lw[0], lw[1], lw[2], lw[3]);
        }

        // wait for B(c); keep B(c+1) in flight
        if (c + 1 < NCHUNKS) { CP_WAIT(1); } else { CP_WAIT(0); }
        __syncthreads();

        // mma for chunk c: 2 K16 steps
        #pragma unroll
        for (int ksl = 0; ksl < 2; ksl++) {
            const int ks = half * 2 + ksl;
            uint32_t BH[2][4], BL[2][4];
            #pragma unroll
            for (int np = 0; np < 2; np++) {
                int n = wid * 32 + np * 16 + (lane & 15);
                int u = ks * 2 + (lane >> 4);
                uint32_t ph = (uint32_t)(n * 128 + ((u ^ (n & 7)) << 4));
                ldsm_x4(BH[np], sbase + SM_BHI + ph);
                ldsm_x4(BL[np], sbase + SM_BLO + ph);
            }
            uint32_t AF[4][4];
            #pragma unroll
            for (int mt = 0; mt < 4; mt++) {
                int r = mt * 16 + (lane & 15);
                int u = ks * 2 + (lane >> 4);
                uint32_t ph = (uint32_t)(r * 128 + ((u ^ (r & 7)) << 4));
                ldsm_x4(AF[mt], sbase + SM_AHI + ph);
            }
            #pragma unroll
            for (int mt = 0; mt < 4; mt++)
                #pragma unroll
                for (int nt = 0; nt < 4; nt++) {
                    mma16816(acc[mt][nt], AF[mt],
                             BH[nt >> 1][nt & 1], BH[nt >> 1][2 + (nt & 1)]);
                    mma16816(acc[mt][nt], AF[mt],
                             BL[nt >> 1][nt & 1], BL[nt >> 1][2 + (nt & 1)]);
                }
            #pragma unroll
            for (int mt = 0; mt < 4; mt++) {
                int r = mt * 16 + (lane & 15);
                int u = ks * 2 + (lane >> 4);
                uint32_t ph = (uint32_t)(r * 128 + ((u ^ (r & 7)) << 4));
                ldsm_x4(AF[mt], sbase + SM_ALO + ph);
            }
            #pragma unroll
            for (int mt = 0; mt < 4; mt++)
                #pragma unroll
                for (int nt = 0; nt < 4; nt++)
                    mma16816(acc[mt][nt], AF[mt],
                             BH[nt >> 1][nt & 1], BH[nt >> 1][2 + (nt & 1)]);
        }
        __syncthreads();   // half reused by chunk c+2's staging

        #pragma unroll
        for (int q = 0; q < 8; q++) xc[q] = xn[q];
    }

    // -------- epilogue: acc + bias -> mask smem (pitch 258) --------
    {
        float* mptr = (float*)smem;
        #pragma unroll
        for (int nt = 0; nt < 4; nt++) {
            int c = wid * 32 + nt * 8 + 2 * (lane & 3);
            float b0 = __ldg(&bias[c]);
            float b1 = __ldg(&bias[c + 1]);
            #pragma unroll
            for (int mt = 0; mt < 4; mt++) {
                int r0 = mt * 16 + (lane >> 2);
                int r1 = r0 + 8;
                mptr[r0 * MASK_PITCH + c]     = acc[mt][nt][0] + b0;
                mptr[r0 * MASK_PITCH + c + 1] = acc[mt][nt][1] + b1;
                mptr[r1 * MASK_PITCH + c]     = acc[mt][nt][2] + b0;
                mptr[r1 * MASK_PITCH + c + 1] = acc[mt][nt][3] + b1;
            }
        }
    }
    __syncthreads();

    // -------- iterations: 1 row per 16-lane group, 2 sets in flight ---------
    // state: t = exp(mask)*w ; num = t^5 ; t *= (1 - num/S) ; w = t*exp(-mask)
    {
        const float* mptr = (const float*)smem;
        const float inv09 = 1.0f / 0.9f;
        const int g = lane & 15;
        const int grp = lane >> 4;
        const int rbase = wid * 8;

        #pragma unroll
        for (int pass = 0; pass < 2; pass++) {
            const int rA = rbase + pass * 4 + grp;
            const int rB = rA + 2;

            const float* rowA = mptr + rA * MASK_PITCH + g * 2;
            const float* rowB = mptr + rB * MASK_PITCH + g * 2;

            u64 T0[8], T1[8];
            #pragma unroll
            for (int pr = 0; pr < 8; pr++) {
                float2 a = *(const float2*)(rowA + 32 * pr);
                float2 b = *(const float2*)(rowB + 32 * pr);
                T0[pr] = pk(__expf(a.x), __expf(a.y));
                T1[pr] = pk(__expf(b.x), __expf(b.y));
            }

            for (int it = 0; it < KITER; it++) {
                u64 n0[8], n1[8];
                #pragma unroll
                for (int pr = 0; pr < 8; pr++) {
                    u64 x2 = mulx2(T0[pr], T0[pr]);
                    u64 x4 = mulx2(x2, x2);
                    n0[pr] = mulx2(x4, T0[pr]);
                    u64 y2 = mulx2(T1[pr], T1[pr]);
                    u64 y4 = mulx2(y2, y2);
                    n1[pr] = mulx2(y4, T1[pr]);
                }
                u64 t0 = addx2(addx2(addx2(n0[0], n0[1]), addx2(n0[2], n0[3])),
                               addx2(addx2(n0[4], n0[5]), addx2(n0[6], n0[7])));
                u64 t1 = addx2(addx2(addx2(n1[0], n1[1]), addx2(n1[2], n1[3])),
                               addx2(addx2(n1[4], n1[5]), addx2(n1[6], n1[7])));
                float a0, a1, b0, b1;
                upk(a0, a1, t0);
                upk(b0, b1, t1);
                float S0 = a0 + a1;
                float S1 = b0 + b1;
                #pragma unroll
                for (int o = 8; o > 0; o >>= 1) {
                    S0 += __shfl_xor_sync(0xffffffffu, S0, o);
                    S1 += __shfl_xor_sync(0xffffffffu, S1, o);
                }
                float q0 = -__fdividef(1.0f, S0);
                float q1 = -__fdividef(1.0f, S1);
                u64 R0 = pk(q0, q0);
                u64 R1 = pk(q1, q1);
                #pragma unroll
                for (int pr = 0; pr < 8; pr++) {
                    T0[pr] = fmax2(mulx2(n0[pr], R0), T0[pr], T0[pr]);
                    T1[pr] = fmax2(mulx2(n1[pr], R1), T1[pr], T1[pr]);
                }
            }

            const int grA = m0 + rA;
            const int grB = m0 + rB;
            if (grA < nrows) {
                const float* fr = feat + (size_t)grA * N_DIM + g * 2;
                float* orow = out + (size_t)grA * N_DIM + g * 2;
                #pragma unroll
                for (int pr = 0; pr < 8; pr++) {
                    float2 a = *(const float2*)(rowA + 32 * pr);
                    u64 wv = mulx2(T0[pr], pk(__expf(-a.x), __expf(-a.y)));
                    float2 f = __ldg((const float2*)(fr + 32 * pr));
                    float wlo, whi;
                    upk(wlo, whi, wv);
                    float2 o2;
                    o2.x = f.x * wlo * inv09;
                    o2.y = f.y * whi * inv09;
                    *(float2*)(orow + 32 * pr) = o2;
                }
            }
            if (grB < nrows) {
                const float* fr = feat + (size_t)grB * N_DIM + g * 2;
                float* orow = out + (size_t)grB * N_DIM + g * 2;
                #pragma unroll
                for (int pr = 0; pr < 8; pr++) {
                    float2 b = *(const float2*)(rowB + 32 * pr);
                    u64 wv = mulx2(T1[pr], pk(__expf(-b.x), __expf(-b.y)));
                    float2 f = __ldg((const float2*)(fr + 32 * pr));
                    float wlo, whi;
                    upk(wlo, whi, wv);
                    float2 o2;
                    o2.x = f.x * wlo * inv09;
                    o2.y = f.y * whi * inv09;
                    *(float2*)(orow + 32 * pr) = o2;
                }
            }
        }
    }
}

// ---- launcher ---------------------------------------------------------------

extern "C" void kernel_launch(void* const* d_in, const int* in_sizes, int n_in,
                              void* d_out, int out_size) {
    const float* feat = (const float*)d_in[0];
    const float* W    = (const float*)d_in[1];
    const float* b    = (const float*)d_in[2];
    float* out        = (float*)d_out;
    const int nrows = in_sizes[0] / N_DIM;
    const int grid = (nrows + MTILE - 1) / MTILE;

    convW_kernel<<<N_DIM, 256>>>(W);

    cudaFuncSetAttribute(sad_kernel,
                         cudaFuncAttributeMaxDynamicSharedMemorySize, SMEM_TOTAL);
    sad_kernel<<<grid, 256, SMEM_TOTAL>>>(feat, b, out, nrows);
}